// round 6
// baseline (speedup 1.0000x reference)
#include <cuda_runtime.h>

// Problem constants
#define BB 8
#define TT 4096
#define DD 1024
#define LL 128                   // output timesteps per block
#define CC (TT / LL)             // 32 chunks
#define LANES (BB * DD)          // 8192 scalar lanes
#define NLB (LANES / 256)        // 32 lane-blocks

__device__ float g_hfinal_scratch[LANES];

// Exact-ish sigmoid (used once for lam only)
__device__ __forceinline__ float fsig_exact_(float v) {
    float e = __expf(-v);
    return __fdividef(1.0f, 1.0f + e);
}

// Hardware tanh (1 MUFU). sigmoid(v) = 0.5 + 0.5*tanh(v/2)
__device__ __forceinline__ float ftanh_(float v) {
    float r;
    asm("tanh.approx.f32 %0, %1;" : "=f"(r) : "f"(v));
    return r;
}
// silu(v) = v*sigmoid(v) = p + p*t,  p = 0.5v, t = tanh(0.5v)
__device__ __forceinline__ float fsilu_(float v) {
    float p = 0.5f * v;
    float t = ftanh_(p);
    return fmaf(p, t, p);
}
// gate(h) = h^2 * sigmoid(h) = q + q*t,  q = 0.5h^2, t = tanh(0.5h)
__device__ __forceinline__ float fgate_(float h) {
    float t = ftanh_(0.5f * h);
    float q = 0.5f * h * h;
    return fmaf(q, t, q);
}

// ---------------------------------------------------------------------------
// Warmup-based chunked recurrence.
//   h_t = lam * (silu(x_t) + h_{t-1}) + b
// Each chunk starts from h=0 at t0-W with lam^W < 2^-33 (clamped to t0 =>
// exact fallback as lam->1; warmup reaching t=0 starts from h0 exactly).
// No inter-block communication; x read ~1.26x, out written once.
// ---------------------------------------------------------------------------
__global__ __launch_bounds__(256) void e55_warm(
    const float* __restrict__ x,
    const float* __restrict__ h0,
    const float* __restrict__ loglam,
    const float* __restrict__ bias,
    float* __restrict__ out,
    float* __restrict__ hfinal)
{
    const int bid = blockIdx.x;
    const int c   = bid >> 5;                 // chunk index [0, CC)
    const int lb  = bid & (NLB - 1);
    const int j   = lb * 256 + threadIdx.x;   // scalar lane [0, LANES)
    const int bi  = j >> 10;                  // batch
    const int d   = j & (DD - 1);             // feature

    const float lam = fsig_exact_(loglam[0]);

    // Required warmup depth: lam^W < 2^-33  =>  W = ceil(33*ln2 / -ln(lam))
    const int t0 = c * LL;
    int W;
    if (lam > 0.999f || lam <= 0.0f) {
        W = t0;                                // exact fallback
    } else {
        float wf = ceilf(__fdividef(22.8739f, -__logf(lam)));  // 33*ln2
        W = (wf >= (float)t0) ? t0 : (int)wf;
    }
    const int ts = t0 - W;

    const float bv = bias[d];
    float h = (ts == 0) ? h0[j] : 0.0f;

    // ---- Warmup: recurrence only, no stores (default cache: L2 reuse) ----
    const float* xp = x + ((bi * TT + ts) * DD + d);
    #pragma unroll 4
    for (int t = 0; t < W; t++) {
        float xv = xp[t * DD];
        h = fmaf(lam, h + fsilu_(xv), bv);
    }

    // ---- Main: recurrence + self-gated output ----
    const float* xm = x + ((bi * TT + t0) * DD + d);
    float*       op = out + ((bi * TT + t0) * DD + d);

    #pragma unroll 1
    for (int tb = 0; tb < LL; tb += 8) {
        float xv[8];
        #pragma unroll
        for (int k = 0; k < 8; k++)
            xv[k] = xm[(tb + k) * DD];         // default policy: neighbors reuse
        #pragma unroll
        for (int k = 0; k < 8; k++) {
            h = fmaf(lam, h + fsilu_(xv[k]), bv);
            __stcs(op + (tb + k) * DD, fgate_(h));
        }
    }

    if (c == CC - 1)
        hfinal[j] = h;
}

// ---------------------------------------------------------------------------
// Launch
// Inputs: x [B,T,D] f32, h0 [B,D] f32, log_lambda [1] f32, b [D] f32
// Output: output [B,T,D] then h_final [B,D] (if space), f32
// ---------------------------------------------------------------------------
extern "C" void kernel_launch(void* const* d_in, const int* in_sizes, int n_in,
                              void* d_out, int out_size)
{
    const float* x      = (const float*)d_in[0];
    const float* h0     = (const float*)d_in[1];
    const float* loglam = (const float*)d_in[2];
    const float* bias   = (const float*)d_in[3];
    float* out = (float*)d_out;

    const long n_output = (long)BB * TT * DD;

    float* hfinal;
    if ((long)out_size >= n_output + LANES) {
        hfinal = out + n_output;
    } else {
        void* p = nullptr;
        cudaGetSymbolAddress(&p, g_hfinal_scratch);
        hfinal = (float*)p;
    }

    e55_warm<<<CC * NLB, 256>>>(x, h0, loglam, bias, out, hfinal);
}